// round 7
// baseline (speedup 1.0000x reference)
#include <cuda_runtime.h>
#include <cuda_fp16.h>

#define NMAX   50000
#define EMAX   800000
#define H      96
#define CIN    128
#define COUT   40
#define NLAYER 5
#define DTC    0.05f

// ---------------- device scratch (static, no allocs) ----------------
__device__ int   g_deg[NMAX];
__device__ int   g_rowptr[NMAX + 1];
__device__ int   g_cursor[NMAX];
__device__ float g_deginv[NMAX];
__device__ int   g_srcs[EMAX];            // stores src*12 (uint4 row offset in fp8 mirror)
// fp16 state ping-pong: interleaved (X,Y) half2 (row = 96 half2 = 24 uint4)
__device__ __align__(16) __half2 g_XY0[(size_t)NMAX * H];
__device__ __align__(16) __half2 g_XY1[(size_t)NMAX * H];
// e4m3 gather mirror ping-pong: (X,Y) fp8 pairs, row = 192 B = 12 uint4
__device__ __align__(16) uint4 g_F80[(size_t)NMAX * 12];
__device__ __align__(16) uint4 g_F81[(size_t)NMAX * 12];

// ---------------- f32x2 packed-FMA helpers ----------------
__device__ __forceinline__ unsigned long long pack2(float v) {
    unsigned long long r; unsigned int u = __float_as_uint(v);
    asm("mov.b64 %0, {%1, %1};" : "=l"(r) : "r"(u));
    return r;
}
__device__ __forceinline__ unsigned long long packxy(float lo, float hi) {
    unsigned long long r;
    asm("mov.b64 %0, {%1, %2};" : "=l"(r) : "f"(lo), "f"(hi));
    return r;
}
__device__ __forceinline__ void unpack2(unsigned long long v, float& a, float& b) {
    unsigned int x, y;
    asm("mov.b64 {%0, %1}, %2;" : "=r"(x), "=r"(y) : "l"(v));
    a = __uint_as_float(x); b = __uint_as_float(y);
}
__device__ __forceinline__ void ffma2(unsigned long long& d,
                                      unsigned long long a, unsigned long long b) {
    asm("fma.rn.f32x2 %0, %1, %2, %0;" : "+l"(d) : "l"(a), "l"(b));
}

// ---------------- fp8 (e4m3) helpers ----------------
__device__ __forceinline__ unsigned short f32_to_e4m3x2(float lo, float hi) {
    unsigned short r;
    asm("cvt.rn.satfinite.e4m3x2.f32 %0, %1, %2;" : "=h"(r) : "f"(hi), "f"(lo));
    return r;
}
__device__ __forceinline__ __half2 e4m3x2_to_h2(unsigned int v16) {
    unsigned int r;
    unsigned short s = (unsigned short)v16;
    asm("cvt.rn.f16x2.e4m3x2 %0, %1;" : "=r"(r) : "h"(s));
    return *(__half2*)&r;
}

// ---------------- CSR build ----------------
__global__ void k_deg(const int* __restrict__ dst, int E) {
    int e = blockIdx.x * blockDim.x + threadIdx.x;
    if (e < E) atomicAdd(&g_deg[dst[e]], 1);
}

__global__ void k_scan(int N) {
    __shared__ int sm[1024];
    int tid = threadIdx.x;
    int per = (N + 1023) >> 10;
    int b = tid * per;
    int e = b + per; if (e > N) e = N; if (b > N) b = N;
    int sum = 0;
    for (int i = b; i < e; ++i) sum += g_deg[i];
    sm[tid] = sum;
    __syncthreads();
    for (int off = 1; off < 1024; off <<= 1) {
        int v = 0;
        if (tid >= off) v = sm[tid - off];
        __syncthreads();
        sm[tid] += v;
        __syncthreads();
    }
    int run = sm[tid] - sum;  // exclusive prefix
    for (int i = b; i < e; ++i) {
        int dg = g_deg[i];
        g_rowptr[i] = run;
        g_cursor[i] = run;
        g_deginv[i] = 1.0f / (float)(dg > 1 ? dg : 1);
        run += dg;
    }
    if (tid == 0) g_rowptr[N] = sm[1023];
}

__global__ void k_scatter(const int* __restrict__ src, const int* __restrict__ dst, int E) {
    int e = blockIdx.x * blockDim.x + threadIdx.x;
    if (e < E) {
        int p = atomicAdd(&g_cursor[dst[e]], 1);
        g_srcs[p] = src[e] * 12;    // pre-scaled uint4 row offset
    }
}

// ---------------- lift (R5 tiling) ----------------
// tanh(x @ [Wx,Wy]) via f32x2; packed lane pair IS (X_c, Y_c).
// 256 threads, block tile 128 rows x 32 pairs, thread tile 8 rows x 2 pairs.
// Writes fp16 state + e4m3 mirror.
__global__ __launch_bounds__(256) void k_lift(
        const float* __restrict__ x,
        const float* __restrict__ Wx, const float* __restrict__ bx,
        const float* __restrict__ Wy, const float* __restrict__ by,
        int N) {
    __shared__ __align__(16) float  xs[128][33];
    __shared__ __align__(16) float2 ws[32][32];
    int tid = threadIdx.x;
    int tx = tid & 15;       // pair group (16), 2 pairs each
    int ty = tid >> 4;       // row group (16), 8 rows each
    int cb = blockIdx.y;     // 0..2
    int row0 = blockIdx.x * 128;

    unsigned long long acc[8][2];
#pragma unroll
    for (int i = 0; i < 8; ++i) { acc[i][0] = 0ull; acc[i][1] = 0ull; }

    for (int kt = 0; kt < CIN; kt += 32) {
#pragma unroll
        for (int j = 0; j < 4; ++j) {
            int f4 = tid + j * 256;
            int r = f4 >> 3;
            int kq = f4 & 7;
            float4 v = make_float4(0.f, 0.f, 0.f, 0.f);
            int gr = row0 + r;
            if (gr < N) v = *(const float4*)(x + (size_t)gr * CIN + kt + kq * 4);
            xs[r][kq * 4 + 0] = v.x; xs[r][kq * 4 + 1] = v.y;
            xs[r][kq * 4 + 2] = v.z; xs[r][kq * 4 + 3] = v.w;
        }
#pragma unroll
        for (int j = 0; j < 4; ++j) {
            int idx = tid + j * 256;
            int k = idx >> 5;
            int p = idx & 31;
            int gp = cb * 32 + p;
            int gk = kt + k;
            ws[k][p] = make_float2(Wx[gk * H + gp], Wy[gk * H + gp]);
        }
        __syncthreads();
#pragma unroll
        for (int k = 0; k < 32; ++k) {
            const unsigned long long* wp =
                reinterpret_cast<const unsigned long long*>(&ws[k][tx * 2]);
            unsigned long long b0 = wp[0], b1 = wp[1];
#pragma unroll
            for (int i = 0; i < 8; ++i) {
                unsigned long long a2 = pack2(xs[ty * 8 + i][k]);
                ffma2(acc[i][0], a2, b0);
                ffma2(acc[i][1], a2, b1);
            }
        }
        __syncthreads();
    }
    int c0 = cb * 32 + tx * 2;
    float bx0 = bx[c0], by0 = by[c0], bx1 = bx[c0 + 1], by1 = by[c0 + 1];
    unsigned int* f8w = (unsigned int*)g_F80;
#pragma unroll
    for (int i = 0; i < 8; ++i) {
        int gr = row0 + ty * 8 + i;
        if (gr < N) {
            float x0, y0, x1, y1;
            unpack2(acc[i][0], x0, y0);
            unpack2(acc[i][1], x1, y1);
            float X0 = tanhf(x0 + bx0), Y0 = tanhf(y0 + by0);
            float X1 = tanhf(x1 + bx1), Y1 = tanhf(y1 + by1);
            __half2 h0 = __floats2half2_rn(X0, Y0);
            __half2 h1 = __floats2half2_rn(X1, Y1);
            uint2 hv;
            hv.x = *(unsigned int*)&h0;
            hv.y = *(unsigned int*)&h1;
            *(uint2*)(&g_XY0[(size_t)gr * H + c0]) = hv;
            unsigned int f8 = (unsigned int)f32_to_e4m3x2(X0, Y0)
                            | ((unsigned int)f32_to_e4m3x2(X1, Y1) << 16);
            f8w[(size_t)gr * 48 + (c0 >> 1)] = f8;
        }
    }
}

// ---------------- one LVConv layer ----------------
// warp per dst node. Lanes 0-11 gather edge A's fp8 row (12 uint4), lanes
// 12-23 edge B's: ONE warp-LDG serves TWO edges. Shuffle-combine, then fp32
// Euler update (lanes 0-11, 8 channels each), write fp16 state + fp8 mirror.
__global__ __launch_bounds__(256) void k_layer(
        const uint4* __restrict__ XYin,     // fp16 rows of 24 uint4
        const uint4* __restrict__ F8in,     // fp8 rows of 12 uint4
        uint4* __restrict__ XYout,
        uint4* __restrict__ F8out,
        const float* __restrict__ al, const float* __restrict__ be,
        const float* __restrict__ ga, const float* __restrict__ de,
        int N) {
    int w = (blockIdx.x * blockDim.x + threadIdx.x) >> 5;
    int lane = threadIdx.x & 31;
    if (w >= N) return;
    int grp = (lane >= 12) ? 1 : 0;         // edge-slot within pair
    int idx = lane - grp * 12;              // uint4 index within row (0..11)
    bool act = lane < 24;
    int s0 = __ldg(&g_rowptr[w]);
    int s1 = __ldg(&g_rowptr[w + 1]);

    __half2 acc[8];
#pragma unroll
    for (int k = 0; k < 8; ++k) acc[k] = __floats2half2_rn(0.f, 0.f);

#define ACC_U4(v)                                             \
    do {                                                      \
        acc[0] = __hadd2(acc[0], e4m3x2_to_h2((v).x));        \
        acc[1] = __hadd2(acc[1], e4m3x2_to_h2((v).x >> 16));  \
        acc[2] = __hadd2(acc[2], e4m3x2_to_h2((v).y));        \
        acc[3] = __hadd2(acc[3], e4m3x2_to_h2((v).y >> 16));  \
        acc[4] = __hadd2(acc[4], e4m3x2_to_h2((v).z));        \
        acc[5] = __hadd2(acc[5], e4m3x2_to_h2((v).z >> 16));  \
        acc[6] = __hadd2(acc[6], e4m3x2_to_h2((v).w));        \
        acc[7] = __hadd2(acc[7], e4m3x2_to_h2((v).w >> 16));  \
    } while (0)

    int e = s0;
    for (; e + 4 <= s1; e += 4) {           // 4 edges per iteration, 2 LDG rounds
        int o0 = __ldg(&g_srcs[e + grp]);
        int o1 = __ldg(&g_srcs[e + 2 + grp]);
        if (act) {
            uint4 v0 = __ldg(F8in + o0 + idx);
            uint4 v1 = __ldg(F8in + o1 + idx);
            ACC_U4(v0);
            ACC_U4(v1);
        }
    }
    if (e + 2 <= s1) {                      // 2-edge tail
        int o0 = __ldg(&g_srcs[e + grp]);
        if (act) {
            uint4 v0 = __ldg(F8in + o0 + idx);
            ACC_U4(v0);
        }
        e += 2;
    }
    if (e < s1) {                           // single-edge tail: group 0 only
        int o0 = __ldg(&g_srcs[e]);
        if (lane < 12) {
            uint4 v0 = __ldg(F8in + o0 + idx);
            ACC_U4(v0);
        }
    }
#undef ACC_U4

    // combine group 1 (lanes 12-23) into group 0 (lanes 0-11)
#pragma unroll
    for (int k = 0; k < 8; ++k) {
        unsigned int u = *(unsigned int*)&acc[k];
        unsigned int v = __shfl_down_sync(0xffffffffu, u, 12);
        acc[k] = __hadd2(acc[k], *(__half2*)&v);
    }
    if (lane >= 12) return;

    float dinv = __ldg(&g_deginv[w]);
    float aggX[8], aggY[8];
#pragma unroll
    for (int k = 0; k < 8; ++k) {
        float2 a = __half22float2(acc[k]);
        aggX[k] = a.x * dinv;
        aggY[k] = a.y * dinv;
    }

    int c0 = idx * 8;                       // 8 channels per lane
    size_t srow = (size_t)w * 24 + idx * 2;
    uint4 sv0 = __ldg(XYin + srow);
    uint4 sv1 = __ldg(XYin + srow + 1);
    float2 sf[8];
    sf[0] = __half22float2(*(__half2*)&sv0.x);
    sf[1] = __half22float2(*(__half2*)&sv0.y);
    sf[2] = __half22float2(*(__half2*)&sv0.z);
    sf[3] = __half22float2(*(__half2*)&sv0.w);
    sf[4] = __half22float2(*(__half2*)&sv1.x);
    sf[5] = __half22float2(*(__half2*)&sv1.y);
    sf[6] = __half22float2(*(__half2*)&sv1.z);
    sf[7] = __half22float2(*(__half2*)&sv1.w);

    float4 al0 = *(const float4*)(al + c0), al1 = *(const float4*)(al + c0 + 4);
    float4 be0 = *(const float4*)(be + c0), be1 = *(const float4*)(be + c0 + 4);
    float4 ga0 = *(const float4*)(ga + c0), ga1 = *(const float4*)(ga + c0 + 4);
    float4 de0 = *(const float4*)(de + c0), de1 = *(const float4*)(de + c0 + 4);
    float alv[8] = {al0.x, al0.y, al0.z, al0.w, al1.x, al1.y, al1.z, al1.w};
    float bev[8] = {be0.x, be0.y, be0.z, be0.w, be1.x, be1.y, be1.z, be1.w};
    float gav[8] = {ga0.x, ga0.y, ga0.z, ga0.w, ga1.x, ga1.y, ga1.z, ga1.w};
    float dev[8] = {de0.x, de0.y, de0.z, de0.w, de1.x, de1.y, de1.z, de1.w};

    float Xn[8], Yn[8];
#pragma unroll
    for (int k = 0; k < 8; ++k) {
        Xn[k] = sf[k].x + DTC * sf[k].x * (alv[k] - bev[k] * aggY[k]);
        Yn[k] = sf[k].y + DTC * sf[k].y * (-gav[k] + dev[k] * aggX[k]);
    }

    __half2 h[8];
#pragma unroll
    for (int k = 0; k < 8; ++k) h[k] = __floats2half2_rn(Xn[k], Yn[k]);
    uint4 o0, o1;
    o0.x = *(unsigned int*)&h[0]; o0.y = *(unsigned int*)&h[1];
    o0.z = *(unsigned int*)&h[2]; o0.w = *(unsigned int*)&h[3];
    o1.x = *(unsigned int*)&h[4]; o1.y = *(unsigned int*)&h[5];
    o1.z = *(unsigned int*)&h[6]; o1.w = *(unsigned int*)&h[7];
    XYout[srow] = o0;
    XYout[srow + 1] = o1;

    uint4 f8;
    f8.x = (unsigned int)f32_to_e4m3x2(Xn[0], Yn[0])
         | ((unsigned int)f32_to_e4m3x2(Xn[1], Yn[1]) << 16);
    f8.y = (unsigned int)f32_to_e4m3x2(Xn[2], Yn[2])
         | ((unsigned int)f32_to_e4m3x2(Xn[3], Yn[3]) << 16);
    f8.z = (unsigned int)f32_to_e4m3x2(Xn[4], Yn[4])
         | ((unsigned int)f32_to_e4m3x2(Xn[5], Yn[5]) << 16);
    f8.w = (unsigned int)f32_to_e4m3x2(Xn[6], Yn[6])
         | ((unsigned int)f32_to_e4m3x2(Xn[7], Yn[7]) << 16);
    F8out[(size_t)w * 12 + idx] = f8;
}

// ---------------- readout: out = [X|Y] @ Wr + br, fp16 state, f32x2 math ----
__global__ __launch_bounds__(128) void k_readout(
        const uint4* __restrict__ XY,       // rows of 24 uint4
        const float* __restrict__ Wr, const float* __restrict__ br,
        float* __restrict__ out, int N) {
    __shared__ float2 xs2[128][33];
    __shared__ float  wsX[32][COUT];
    __shared__ float  wsY[32][COUT];
    int tid = threadIdx.x;
    int tx = tid & 7;
    int ty = tid >> 3;
    int row0 = blockIdx.x * 128;
    unsigned long long acc2[4][5];
#pragma unroll
    for (int p = 0; p < 4; ++p)
#pragma unroll
        for (int j = 0; j < 5; ++j) acc2[p][j] = 0ull;

    for (int kt = 0; kt < H; kt += 32) {
#pragma unroll
        for (int j = 0; j < 8; ++j) {
            int u4 = tid + j * 128;
            int r = u4 >> 3;
            int q = u4 & 7;
            int gr = row0 + r;
            uint4 v = make_uint4(0u, 0u, 0u, 0u);
            if (gr < N) v = __ldg(XY + (size_t)gr * 24 + (kt >> 2) + q);
            int cc = q * 4;
            xs2[r][cc + 0] = __half22float2(*(__half2*)&v.x);
            xs2[r][cc + 1] = __half22float2(*(__half2*)&v.y);
            xs2[r][cc + 2] = __half22float2(*(__half2*)&v.z);
            xs2[r][cc + 3] = __half22float2(*(__half2*)&v.w);
        }
#pragma unroll
        for (int j = 0; j < 10; ++j) {
            int idx = tid + j * 128;
            if (idx < 32 * COUT) {
                int k = idx / COUT;
                int c = idx - k * COUT;
                wsX[k][c] = Wr[(size_t)(kt + k) * COUT + c];
                wsY[k][c] = Wr[(size_t)(H + kt + k) * COUT + c];
            }
        }
        __syncthreads();
#pragma unroll
        for (int k = 0; k < 32; ++k) {
            float2 xv[8];
#pragma unroll
            for (int i = 0; i < 8; ++i) xv[i] = xs2[ty * 8 + i][k];
            unsigned long long XA[4], YA[4];
#pragma unroll
            for (int p = 0; p < 4; ++p) {
                XA[p] = packxy(xv[2 * p].x, xv[2 * p + 1].x);
                YA[p] = packxy(xv[2 * p].y, xv[2 * p + 1].y);
            }
#pragma unroll
            for (int j = 0; j < 5; ++j) {
                unsigned long long wxj = pack2(wsX[k][tx * 5 + j]);
                unsigned long long wyj = pack2(wsY[k][tx * 5 + j]);
#pragma unroll
                for (int p = 0; p < 4; ++p) {
                    ffma2(acc2[p][j], XA[p], wxj);
                    ffma2(acc2[p][j], YA[p], wyj);
                }
            }
        }
        __syncthreads();
    }
#pragma unroll
    for (int p = 0; p < 4; ++p) {
        int gr0 = row0 + ty * 8 + 2 * p;
#pragma unroll
        for (int j = 0; j < 5; ++j) {
            float vlo, vhi;
            unpack2(acc2[p][j], vlo, vhi);
            float bb = br[tx * 5 + j];
            if (gr0 < N)     out[(size_t)gr0 * COUT + tx * 5 + j] = vlo + bb;
            if (gr0 + 1 < N) out[(size_t)(gr0 + 1) * COUT + tx * 5 + j] = vhi + bb;
        }
    }
}

// ---------------- launch ----------------
extern "C" void kernel_launch(void* const* d_in, const int* in_sizes, int n_in,
                              void* d_out, int out_size) {
    const float* x  = (const float*)d_in[0];
    const int*   ei = (const int*)d_in[1];
    const float* Wx = (const float*)d_in[2];
    const float* bx = (const float*)d_in[3];
    const float* Wy = (const float*)d_in[4];
    const float* by = (const float*)d_in[5];
    const float* al = (const float*)d_in[6];
    const float* be = (const float*)d_in[7];
    const float* ga = (const float*)d_in[8];
    const float* de = (const float*)d_in[9];
    const float* Wr = (const float*)d_in[10];
    const float* br = (const float*)d_in[11];
    float* out = (float*)d_out;

    int N = in_sizes[0] / CIN;
    int E = in_sizes[1] / 2;
    if (N > NMAX) N = NMAX;
    if (E > EMAX) E = EMAX;
    const int* srcp = ei;
    const int* dstp = ei + E;

    void* degp;
    cudaGetSymbolAddress(&degp, g_deg);
    cudaMemsetAsync(degp, 0, (size_t)N * sizeof(int));

    k_deg<<<(E + 255) / 256, 256>>>(dstp, E);
    k_scan<<<1, 1024>>>(N);
    k_scatter<<<(E + 255) / 256, 256>>>(srcp, dstp, E);

    dim3 gl((N + 127) / 128, 3);
    k_lift<<<gl, 256>>>(x, Wx, bx, Wy, by, N);

    uint4* XYb[2]; uint4* F8b[2];
    cudaGetSymbolAddress((void**)&XYb[0], g_XY0);
    cudaGetSymbolAddress((void**)&XYb[1], g_XY1);
    cudaGetSymbolAddress((void**)&F8b[0], g_F80);
    cudaGetSymbolAddress((void**)&F8b[1], g_F81);

    int layerBlocks = (N * 32 + 255) / 256;
    for (int l = 0; l < NLAYER; ++l) {
        k_layer<<<layerBlocks, 256>>>(XYb[l & 1], F8b[l & 1],
                                      XYb[(l + 1) & 1], F8b[(l + 1) & 1],
                                      al + l * H, be + l * H, ga + l * H, de + l * H, N);
    }
    k_readout<<<(N + 127) / 128, 128>>>(XYb[NLAYER & 1], Wr, br, out, N);
}

// round 8
// speedup vs baseline: 1.5633x; 1.5633x over previous
#include <cuda_runtime.h>
#include <cuda_fp16.h>

#define NMAX   50000
#define EMAX   800000
#define H      96
#define CIN    128
#define COUT   40
#define NLAYER 5
#define DTC    0.05f

// ---------------- device scratch (static, no allocs) ----------------
__device__ int   g_deg[NMAX];
__device__ int   g_rowptr[NMAX + 1];
__device__ int   g_cursor[NMAX];
__device__ float g_deginv[NMAX];
__device__ int   g_srcs[EMAX];            // stores src*24 (uint4 row offset)
__device__ int   g_excl[NMAX];            // per-block-local exclusive prefix
__device__ int   g_bsum[64];              // per-block degree sums
__device__ int   g_bexcl[64];             // scanned block offsets
// fp16 state ping-pong: interleaved (X,Y) half2 (row = 96 half2 = 24 uint4)
__device__ __align__(16) __half2 g_XY0[(size_t)NMAX * H];
__device__ __align__(16) __half2 g_XY1[(size_t)NMAX * H];

// ---------------- f32x2 packed-FMA helpers ----------------
__device__ __forceinline__ unsigned long long pack2(float v) {
    unsigned long long r; unsigned int u = __float_as_uint(v);
    asm("mov.b64 %0, {%1, %1};" : "=l"(r) : "r"(u));
    return r;
}
__device__ __forceinline__ unsigned long long packxy(float lo, float hi) {
    unsigned long long r;
    asm("mov.b64 %0, {%1, %2};" : "=l"(r) : "f"(lo), "f"(hi));
    return r;
}
__device__ __forceinline__ void unpack2(unsigned long long v, float& a, float& b) {
    unsigned int x, y;
    asm("mov.b64 {%0, %1}, %2;" : "=r"(x), "=r"(y) : "l"(v));
    a = __uint_as_float(x); b = __uint_as_float(y);
}
__device__ __forceinline__ void ffma2(unsigned long long& d,
                                      unsigned long long a, unsigned long long b) {
    asm("fma.rn.f32x2 %0, %1, %2, %0;" : "+l"(d) : "l"(a), "l"(b));
}

// ---------------- CSR build ----------------
__global__ void k_deg(const int* __restrict__ dst, int E) {
    int e = blockIdx.x * blockDim.x + threadIdx.x;
    if (e < E) atomicAdd(&g_deg[dst[e]], 1);
}

// stage 1: per-block (1024-wide) inclusive scan of degrees -> local exclusive + block sums
__global__ __launch_bounds__(1024) void k_scan1(int N) {
    __shared__ int sm[1024];
    int tid = threadIdx.x;
    int t = blockIdx.x * 1024 + tid;
    int d = (t < N) ? g_deg[t] : 0;
    sm[tid] = d;
    __syncthreads();
#pragma unroll
    for (int off = 1; off < 1024; off <<= 1) {
        int v = 0;
        if (tid >= off) v = sm[tid - off];
        __syncthreads();
        sm[tid] += v;
        __syncthreads();
    }
    if (t < N) g_excl[t] = sm[tid] - d;
    if (tid == 1023) g_bsum[blockIdx.x] = sm[1023];
}

// stage 2: serial scan of block sums (<= 64 entries)
__global__ void k_scan2(int NB, int N) {
    if (threadIdx.x == 0) {
        int run = 0;
        for (int b = 0; b < NB; ++b) {
            g_bexcl[b] = run;
            run += g_bsum[b];
        }
        g_rowptr[N] = run;
    }
}

// stage 3: write rowptr / cursor / deginv
__global__ __launch_bounds__(1024) void k_scan3(int N) {
    int t = blockIdx.x * 1024 + threadIdx.x;
    if (t < N) {
        int rp = g_bexcl[blockIdx.x] + g_excl[t];
        g_rowptr[t] = rp;
        g_cursor[t] = rp;
        int dg = g_deg[t];
        g_deginv[t] = 1.0f / (float)(dg > 1 ? dg : 1);
    }
}

__global__ void k_scatter(const int* __restrict__ src, const int* __restrict__ dst, int E) {
    int e = blockIdx.x * blockDim.x + threadIdx.x;
    if (e < E) {
        int p = atomicAdd(&g_cursor[dst[e]], 1);
        g_srcs[p] = src[e] * 24;    // pre-scaled uint4 row offset
    }
}

// ---------------- lift ----------------
// tanh(x @ [Wx,Wy]) via f32x2; packed lane pair IS (X_c, Y_c).
// 256 threads, block tile 128 rows x 32 pairs, thread tile 8 rows x 2 pairs.
__global__ __launch_bounds__(256, 3) void k_lift(
        const float* __restrict__ x,
        const float* __restrict__ Wx, const float* __restrict__ bx,
        const float* __restrict__ Wy, const float* __restrict__ by,
        int N) {
    __shared__ __align__(16) float  xs[128][33];
    __shared__ __align__(16) float2 ws[32][32];
    int tid = threadIdx.x;
    int tx = tid & 15;       // pair group (16), 2 pairs each
    int ty = tid >> 4;       // row group (16), 8 rows each
    int cb = blockIdx.y;     // 0..2
    int row0 = blockIdx.x * 128;

    unsigned long long acc[8][2];
#pragma unroll
    for (int i = 0; i < 8; ++i) { acc[i][0] = 0ull; acc[i][1] = 0ull; }

    for (int kt = 0; kt < CIN; kt += 32) {
#pragma unroll
        for (int j = 0; j < 4; ++j) {
            int f4 = tid + j * 256;
            int r = f4 >> 3;
            int kq = f4 & 7;
            float4 v = make_float4(0.f, 0.f, 0.f, 0.f);
            int gr = row0 + r;
            if (gr < N) v = *(const float4*)(x + (size_t)gr * CIN + kt + kq * 4);
            xs[r][kq * 4 + 0] = v.x; xs[r][kq * 4 + 1] = v.y;
            xs[r][kq * 4 + 2] = v.z; xs[r][kq * 4 + 3] = v.w;
        }
#pragma unroll
        for (int j = 0; j < 4; ++j) {
            int idx = tid + j * 256;
            int k = idx >> 5;
            int p = idx & 31;
            int gp = cb * 32 + p;
            int gk = kt + k;
            ws[k][p] = make_float2(Wx[gk * H + gp], Wy[gk * H + gp]);
        }
        __syncthreads();
#pragma unroll
        for (int k = 0; k < 32; ++k) {
            const unsigned long long* wp =
                reinterpret_cast<const unsigned long long*>(&ws[k][tx * 2]);
            unsigned long long b0 = wp[0], b1 = wp[1];
#pragma unroll
            for (int i = 0; i < 8; ++i) {
                unsigned long long a2 = pack2(xs[ty * 8 + i][k]);
                ffma2(acc[i][0], a2, b0);
                ffma2(acc[i][1], a2, b1);
            }
        }
        __syncthreads();
    }
    int c0 = cb * 32 + tx * 2;
    float bx0 = bx[c0], by0 = by[c0], bx1 = bx[c0 + 1], by1 = by[c0 + 1];
#pragma unroll
    for (int i = 0; i < 8; ++i) {
        int gr = row0 + ty * 8 + i;
        if (gr < N) {
            float x0, y0, x1, y1;
            unpack2(acc[i][0], x0, y0);
            unpack2(acc[i][1], x1, y1);
            __half2 h0 = __floats2half2_rn(tanhf(x0 + bx0), tanhf(y0 + by0));
            __half2 h1 = __floats2half2_rn(tanhf(x1 + bx1), tanhf(y1 + by1));
            uint2 hv;
            hv.x = *(unsigned int*)&h0;
            hv.y = *(unsigned int*)&h1;
            *(uint2*)(&g_XY0[(size_t)gr * H + c0]) = hv;
        }
    }
}

// ---------------- one LVConv layer (R5-proven form) ----------------
// warp per dst node. Gather: lanes 0..23 each load the full row slice as ONE
// LDG.128 (uint4 = 4 half2 = 4 channel-pairs), accumulate with HADD2.
// Epilogue: fp32 Euler update from the fp16 state row, write one uint4.
__global__ __launch_bounds__(256) void k_layer(
        const uint4* __restrict__ XYin,     // rows of 24 uint4
        uint4* __restrict__ XYout,
        const float* __restrict__ al, const float* __restrict__ be,
        const float* __restrict__ ga, const float* __restrict__ de,
        int N) {
    int w = (blockIdx.x * blockDim.x + threadIdx.x) >> 5;
    int lane = threadIdx.x & 31;
    if (w >= N) return;
    bool act = lane < 24;
    int s0 = __ldg(&g_rowptr[w]);
    int s1 = __ldg(&g_rowptr[w + 1]);

    __half2 acc0 = __floats2half2_rn(0.f, 0.f);
    __half2 acc1 = acc0, acc2 = acc0, acc3 = acc0;

    int e = s0;
    for (; e + 4 <= s1; e += 4) {
        int oA = __ldg(&g_srcs[e + 0]);
        int oB = __ldg(&g_srcs[e + 1]);
        int oC = __ldg(&g_srcs[e + 2]);
        int oD = __ldg(&g_srcs[e + 3]);
        if (act) {
            uint4 vA = __ldg(XYin + oA + lane);
            uint4 vB = __ldg(XYin + oB + lane);
            uint4 vC = __ldg(XYin + oC + lane);
            uint4 vD = __ldg(XYin + oD + lane);
            acc0 = __hadd2(acc0, __hadd2(__hadd2(*(__half2*)&vA.x, *(__half2*)&vB.x),
                                         __hadd2(*(__half2*)&vC.x, *(__half2*)&vD.x)));
            acc1 = __hadd2(acc1, __hadd2(__hadd2(*(__half2*)&vA.y, *(__half2*)&vB.y),
                                         __hadd2(*(__half2*)&vC.y, *(__half2*)&vD.y)));
            acc2 = __hadd2(acc2, __hadd2(__hadd2(*(__half2*)&vA.z, *(__half2*)&vB.z),
                                         __hadd2(*(__half2*)&vC.z, *(__half2*)&vD.z)));
            acc3 = __hadd2(acc3, __hadd2(__hadd2(*(__half2*)&vA.w, *(__half2*)&vB.w),
                                         __hadd2(*(__half2*)&vC.w, *(__half2*)&vD.w)));
        }
    }
    for (; e < s1; ++e) {
        int o = __ldg(&g_srcs[e]);
        if (act) {
            uint4 v = __ldg(XYin + o + lane);
            acc0 = __hadd2(acc0, *(__half2*)&v.x);
            acc1 = __hadd2(acc1, *(__half2*)&v.y);
            acc2 = __hadd2(acc2, *(__half2*)&v.z);
            acc3 = __hadd2(acc3, *(__half2*)&v.w);
        }
    }
    if (!act) return;

    float dinv = __ldg(&g_deginv[w]);
    float2 a0 = __half22float2(acc0);
    float2 a1 = __half22float2(acc1);
    float2 a2 = __half22float2(acc2);
    float2 a3 = __half22float2(acc3);
    float aggX[4] = {a0.x * dinv, a1.x * dinv, a2.x * dinv, a3.x * dinv};
    float aggY[4] = {a0.y * dinv, a1.y * dinv, a2.y * dinv, a3.y * dinv};

    int c0 = lane * 4;
    size_t rbase = (size_t)w * 24 + lane;
    uint4 sv = __ldg(XYin + rbase);
    float2 s0f = __half22float2(*(__half2*)&sv.x);
    float2 s1f = __half22float2(*(__half2*)&sv.y);
    float2 s2f = __half22float2(*(__half2*)&sv.z);
    float2 s3f = __half22float2(*(__half2*)&sv.w);

    float4 alv = *(const float4*)(al + c0);
    float4 bev = *(const float4*)(be + c0);
    float4 gav = *(const float4*)(ga + c0);
    float4 dev = *(const float4*)(de + c0);

    float Xn0 = s0f.x + DTC * s0f.x * (alv.x - bev.x * aggY[0]);
    float Yn0 = s0f.y + DTC * s0f.y * (-gav.x + dev.x * aggX[0]);
    float Xn1 = s1f.x + DTC * s1f.x * (alv.y - bev.y * aggY[1]);
    float Yn1 = s1f.y + DTC * s1f.y * (-gav.y + dev.y * aggX[1]);
    float Xn2 = s2f.x + DTC * s2f.x * (alv.z - bev.z * aggY[2]);
    float Yn2 = s2f.y + DTC * s2f.y * (-gav.z + dev.z * aggX[2]);
    float Xn3 = s3f.x + DTC * s3f.x * (alv.w - bev.w * aggY[3]);
    float Yn3 = s3f.y + DTC * s3f.y * (-gav.w + dev.w * aggX[3]);

    __half2 h0 = __floats2half2_rn(Xn0, Yn0);
    __half2 h1 = __floats2half2_rn(Xn1, Yn1);
    __half2 h2 = __floats2half2_rn(Xn2, Yn2);
    __half2 h3 = __floats2half2_rn(Xn3, Yn3);
    uint4 hv;
    hv.x = *(unsigned int*)&h0; hv.y = *(unsigned int*)&h1;
    hv.z = *(unsigned int*)&h2; hv.w = *(unsigned int*)&h3;
    XYout[rbase] = hv;
}

// ---------------- readout: out = [X|Y] @ Wr + br, fp16 state, f32x2 math ----
__global__ __launch_bounds__(128) void k_readout(
        const uint4* __restrict__ XY,       // rows of 24 uint4
        const float* __restrict__ Wr, const float* __restrict__ br,
        float* __restrict__ out, int N) {
    __shared__ float2 xs2[128][33];
    __shared__ float  wsX[32][COUT];
    __shared__ float  wsY[32][COUT];
    int tid = threadIdx.x;
    int tx = tid & 7;
    int ty = tid >> 3;
    int row0 = blockIdx.x * 128;
    unsigned long long acc2[4][5];
#pragma unroll
    for (int p = 0; p < 4; ++p)
#pragma unroll
        for (int j = 0; j < 5; ++j) acc2[p][j] = 0ull;

    for (int kt = 0; kt < H; kt += 32) {
#pragma unroll
        for (int j = 0; j < 8; ++j) {
            int u4 = tid + j * 128;
            int r = u4 >> 3;
            int q = u4 & 7;
            int gr = row0 + r;
            uint4 v = make_uint4(0u, 0u, 0u, 0u);
            if (gr < N) v = __ldg(XY + (size_t)gr * 24 + (kt >> 2) + q);
            int cc = q * 4;
            xs2[r][cc + 0] = __half22float2(*(__half2*)&v.x);
            xs2[r][cc + 1] = __half22float2(*(__half2*)&v.y);
            xs2[r][cc + 2] = __half22float2(*(__half2*)&v.z);
            xs2[r][cc + 3] = __half22float2(*(__half2*)&v.w);
        }
#pragma unroll
        for (int j = 0; j < 10; ++j) {
            int idx = tid + j * 128;
            if (idx < 32 * COUT) {
                int k = idx / COUT;
                int c = idx - k * COUT;
                wsX[k][c] = Wr[(size_t)(kt + k) * COUT + c];
                wsY[k][c] = Wr[(size_t)(H + kt + k) * COUT + c];
            }
        }
        __syncthreads();
#pragma unroll
        for (int k = 0; k < 32; ++k) {
            float2 xv[8];
#pragma unroll
            for (int i = 0; i < 8; ++i) xv[i] = xs2[ty * 8 + i][k];
            unsigned long long XA[4], YA[4];
#pragma unroll
            for (int p = 0; p < 4; ++p) {
                XA[p] = packxy(xv[2 * p].x, xv[2 * p + 1].x);
                YA[p] = packxy(xv[2 * p].y, xv[2 * p + 1].y);
            }
#pragma unroll
            for (int j = 0; j < 5; ++j) {
                unsigned long long wxj = pack2(wsX[k][tx * 5 + j]);
                unsigned long long wyj = pack2(wsY[k][tx * 5 + j]);
#pragma unroll
                for (int p = 0; p < 4; ++p) {
                    ffma2(acc2[p][j], XA[p], wxj);
                    ffma2(acc2[p][j], YA[p], wyj);
                }
            }
        }
        __syncthreads();
    }
#pragma unroll
    for (int p = 0; p < 4; ++p) {
        int gr0 = row0 + ty * 8 + 2 * p;
#pragma unroll
        for (int j = 0; j < 5; ++j) {
            float vlo, vhi;
            unpack2(acc2[p][j], vlo, vhi);
            float bb = br[tx * 5 + j];
            if (gr0 < N)     out[(size_t)gr0 * COUT + tx * 5 + j] = vlo + bb;
            if (gr0 + 1 < N) out[(size_t)(gr0 + 1) * COUT + tx * 5 + j] = vhi + bb;
        }
    }
}

// ---------------- launch ----------------
extern "C" void kernel_launch(void* const* d_in, const int* in_sizes, int n_in,
                              void* d_out, int out_size) {
    const float* x  = (const float*)d_in[0];
    const int*   ei = (const int*)d_in[1];
    const float* Wx = (const float*)d_in[2];
    const float* bx = (const float*)d_in[3];
    const float* Wy = (const float*)d_in[4];
    const float* by = (const float*)d_in[5];
    const float* al = (const float*)d_in[6];
    const float* be = (const float*)d_in[7];
    const float* ga = (const float*)d_in[8];
    const float* de = (const float*)d_in[9];
    const float* Wr = (const float*)d_in[10];
    const float* br = (const float*)d_in[11];
    float* out = (float*)d_out;

    int N = in_sizes[0] / CIN;
    int E = in_sizes[1] / 2;
    if (N > NMAX) N = NMAX;
    if (E > EMAX) E = EMAX;
    const int* srcp = ei;
    const int* dstp = ei + E;

    void* degp;
    cudaGetSymbolAddress(&degp, g_deg);
    cudaMemsetAsync(degp, 0, (size_t)N * sizeof(int));

    int NB = (N + 1023) >> 10;
    k_deg<<<(E + 255) / 256, 256>>>(dstp, E);
    k_scan1<<<NB, 1024>>>(N);
    k_scan2<<<1, 32>>>(NB, N);
    k_scan3<<<NB, 1024>>>(N);
    k_scatter<<<(E + 255) / 256, 256>>>(srcp, dstp, E);

    dim3 gl((N + 127) / 128, 3);
    k_lift<<<gl, 256>>>(x, Wx, bx, Wy, by, N);

    uint4* XYb[2];
    cudaGetSymbolAddress((void**)&XYb[0], g_XY0);
    cudaGetSymbolAddress((void**)&XYb[1], g_XY1);

    int layerBlocks = (N * 32 + 255) / 256;
    for (int l = 0; l < NLAYER; ++l) {
        k_layer<<<layerBlocks, 256>>>(XYb[l & 1], XYb[(l + 1) & 1],
                                      al + l * H, be + l * H, ga + l * H, de + l * H, N);
    }
    k_readout<<<(N + 127) / 128, 128>>>(XYb[NLAYER & 1], Wr, br, out, N);
}

// round 9
// speedup vs baseline: 1.6331x; 1.0447x over previous
#include <cuda_runtime.h>
#include <cuda_fp16.h>

#define NMAX   50000
#define EMAX   800000
#define H      96
#define CIN    128
#define COUT   40
#define NLAYER 5
#define DTC    0.05f

// ---------------- device scratch (static, no allocs) ----------------
__device__ int   g_deg[NMAX];
__device__ int   g_rowptr[NMAX + 1];
__device__ int   g_cursor[NMAX];
__device__ float g_deginv[NMAX];
__device__ int   g_srcs[EMAX];            // stores src*24 (uint4 row offset)
__device__ int   g_excl[NMAX];            // per-block-local exclusive prefix
__device__ int   g_bsum[64];              // per-block degree sums
__device__ int   g_bexcl[64];             // scanned block offsets
// fp16 state ping-pong: interleaved (X,Y) half2 (row = 96 half2 = 24 uint4)
__device__ __align__(16) __half2 g_XY0[(size_t)NMAX * H];
__device__ __align__(16) __half2 g_XY1[(size_t)NMAX * H];

// ---------------- f32x2 packed-FMA helpers ----------------
__device__ __forceinline__ unsigned long long pack2(float v) {
    unsigned long long r; unsigned int u = __float_as_uint(v);
    asm("mov.b64 %0, {%1, %1};" : "=l"(r) : "r"(u));
    return r;
}
__device__ __forceinline__ unsigned long long packxy(float lo, float hi) {
    unsigned long long r;
    asm("mov.b64 %0, {%1, %2};" : "=l"(r) : "f"(lo), "f"(hi));
    return r;
}
__device__ __forceinline__ void unpack2(unsigned long long v, float& a, float& b) {
    unsigned int x, y;
    asm("mov.b64 {%0, %1}, %2;" : "=r"(x), "=r"(y) : "l"(v));
    a = __uint_as_float(x); b = __uint_as_float(y);
}
__device__ __forceinline__ void ffma2(unsigned long long& d,
                                      unsigned long long a, unsigned long long b) {
    asm("fma.rn.f32x2 %0, %1, %2, %0;" : "+l"(d) : "l"(a), "l"(b));
}

// ---------------- CSR build ----------------
__global__ void k_deg(const int* __restrict__ dst, int E) {
    int e = blockIdx.x * blockDim.x + threadIdx.x;
    if (e < E) atomicAdd(&g_deg[dst[e]], 1);
}

// stage 1: per-block (1024) scan of degrees via warp shuffles (2 barriers)
__global__ __launch_bounds__(1024) void k_scan1(int N) {
    __shared__ int wsum[32];
    int tid = threadIdx.x;
    int t = blockIdx.x * 1024 + tid;
    int d = (t < N) ? g_deg[t] : 0;
    int lane = tid & 31, wid = tid >> 5;
    int v = d;
#pragma unroll
    for (int off = 1; off < 32; off <<= 1) {
        int u = __shfl_up_sync(0xffffffffu, v, off);
        if (lane >= off) v += u;
    }
    if (lane == 31) wsum[wid] = v;
    __syncthreads();
    if (wid == 0) {
        int s = wsum[lane];
#pragma unroll
        for (int off = 1; off < 32; off <<= 1) {
            int u = __shfl_up_sync(0xffffffffu, s, off);
            if (lane >= off) s += u;
        }
        wsum[lane] = s;
    }
    __syncthreads();
    int incl = v + (wid > 0 ? wsum[wid - 1] : 0);
    if (t < N) g_excl[t] = incl - d;
    if (tid == 1023) g_bsum[blockIdx.x] = incl;
}

// stage 2: scan of block sums (<= 64 entries), one warp
__global__ void k_scan2(int NB, int N) {
    int lane = threadIdx.x;   // 64 threads
    int s = (lane < NB) ? g_bsum[lane] : 0;
    int v = s;
#pragma unroll
    for (int off = 1; off < 64; off <<= 1) {
        int u = __shfl_up_sync(0xffffffffu, v, off);   // within 32-lane warp
        if ((lane & 31) >= off) v += u;
    }
    __shared__ int w0sum;
    if (lane == 31) w0sum = v;
    __syncthreads();
    int incl = v + ((lane >= 32) ? w0sum : 0);
    if (lane < NB) g_bexcl[lane] = incl - s;
    if (lane == NB - 1) g_rowptr[N] = incl;
}

// stage 3: write rowptr / cursor / deginv
__global__ __launch_bounds__(256) void k_scan3(int N) {
    int t = blockIdx.x * 256 + threadIdx.x;
    if (t < N) {
        int rp = g_bexcl[t >> 10] + g_excl[t];
        g_rowptr[t] = rp;
        g_cursor[t] = rp;
        int dg = g_deg[t];
        g_deginv[t] = 1.0f / (float)(dg > 1 ? dg : 1);
    }
}

__global__ void k_scatter(const int* __restrict__ src, const int* __restrict__ dst, int E) {
    int e = blockIdx.x * blockDim.x + threadIdx.x;
    if (e < E) {
        int p = atomicAdd(&g_cursor[dst[e]], 1);
        g_srcs[p] = src[e] * 24;    // pre-scaled uint4 row offset
    }
}

// ---------------- lift ----------------
// tanh(x @ [Wx,Wy]) via f32x2; packed lane pair IS (X_c, Y_c).
// 256 threads, block tile 128 rows x 32 pairs, thread tile 8 rows x 2 pairs.
__global__ __launch_bounds__(256, 3) void k_lift(
        const float* __restrict__ x,
        const float* __restrict__ Wx, const float* __restrict__ bx,
        const float* __restrict__ Wy, const float* __restrict__ by,
        int N) {
    __shared__ __align__(16) float  xs[128][33];
    __shared__ __align__(16) float2 ws[32][32];
    int tid = threadIdx.x;
    int tx = tid & 15;
    int ty = tid >> 4;
    int cb = blockIdx.y;
    int row0 = blockIdx.x * 128;

    unsigned long long acc[8][2];
#pragma unroll
    for (int i = 0; i < 8; ++i) { acc[i][0] = 0ull; acc[i][1] = 0ull; }

    for (int kt = 0; kt < CIN; kt += 32) {
#pragma unroll
        for (int j = 0; j < 4; ++j) {
            int f4 = tid + j * 256;
            int r = f4 >> 3;
            int kq = f4 & 7;
            float4 v = make_float4(0.f, 0.f, 0.f, 0.f);
            int gr = row0 + r;
            if (gr < N) v = *(const float4*)(x + (size_t)gr * CIN + kt + kq * 4);
            xs[r][kq * 4 + 0] = v.x; xs[r][kq * 4 + 1] = v.y;
            xs[r][kq * 4 + 2] = v.z; xs[r][kq * 4 + 3] = v.w;
        }
#pragma unroll
        for (int j = 0; j < 4; ++j) {
            int idx = tid + j * 256;
            int k = idx >> 5;
            int p = idx & 31;
            int gp = cb * 32 + p;
            int gk = kt + k;
            ws[k][p] = make_float2(Wx[gk * H + gp], Wy[gk * H + gp]);
        }
        __syncthreads();
#pragma unroll
        for (int k = 0; k < 32; ++k) {
            const unsigned long long* wp =
                reinterpret_cast<const unsigned long long*>(&ws[k][tx * 2]);
            unsigned long long b0 = wp[0], b1 = wp[1];
#pragma unroll
            for (int i = 0; i < 8; ++i) {
                unsigned long long a2 = pack2(xs[ty * 8 + i][k]);
                ffma2(acc[i][0], a2, b0);
                ffma2(acc[i][1], a2, b1);
            }
        }
        __syncthreads();
    }
    int c0 = cb * 32 + tx * 2;
    float bx0 = bx[c0], by0 = by[c0], bx1 = bx[c0 + 1], by1 = by[c0 + 1];
#pragma unroll
    for (int i = 0; i < 8; ++i) {
        int gr = row0 + ty * 8 + i;
        if (gr < N) {
            float x0, y0, x1, y1;
            unpack2(acc[i][0], x0, y0);
            unpack2(acc[i][1], x1, y1);
            __half2 h0 = __floats2half2_rn(tanhf(x0 + bx0), tanhf(y0 + by0));
            __half2 h1 = __floats2half2_rn(tanhf(x1 + bx1), tanhf(y1 + by1));
            uint2 hv;
            hv.x = *(unsigned int*)&h0;
            hv.y = *(unsigned int*)&h1;
            *(uint2*)(&g_XY0[(size_t)gr * H + c0]) = hv;
        }
    }
}

// ---------------- one LVConv layer (R5-proven form) ----------------
__global__ __launch_bounds__(256) void k_layer(
        const uint4* __restrict__ XYin,     // rows of 24 uint4
        uint4* __restrict__ XYout,
        const float* __restrict__ al, const float* __restrict__ be,
        const float* __restrict__ ga, const float* __restrict__ de,
        int N) {
    int w = (blockIdx.x * blockDim.x + threadIdx.x) >> 5;
    int lane = threadIdx.x & 31;
    if (w >= N) return;
    bool act = lane < 24;
    int s0 = __ldg(&g_rowptr[w]);
    int s1 = __ldg(&g_rowptr[w + 1]);

    __half2 acc0 = __floats2half2_rn(0.f, 0.f);
    __half2 acc1 = acc0, acc2 = acc0, acc3 = acc0;

    int e = s0;
    for (; e + 4 <= s1; e += 4) {
        int oA = __ldg(&g_srcs[e + 0]);
        int oB = __ldg(&g_srcs[e + 1]);
        int oC = __ldg(&g_srcs[e + 2]);
        int oD = __ldg(&g_srcs[e + 3]);
        if (act) {
            uint4 vA = __ldg(XYin + oA + lane);
            uint4 vB = __ldg(XYin + oB + lane);
            uint4 vC = __ldg(XYin + oC + lane);
            uint4 vD = __ldg(XYin + oD + lane);
            acc0 = __hadd2(acc0, __hadd2(__hadd2(*(__half2*)&vA.x, *(__half2*)&vB.x),
                                         __hadd2(*(__half2*)&vC.x, *(__half2*)&vD.x)));
            acc1 = __hadd2(acc1, __hadd2(__hadd2(*(__half2*)&vA.y, *(__half2*)&vB.y),
                                         __hadd2(*(__half2*)&vC.y, *(__half2*)&vD.y)));
            acc2 = __hadd2(acc2, __hadd2(__hadd2(*(__half2*)&vA.z, *(__half2*)&vB.z),
                                         __hadd2(*(__half2*)&vC.z, *(__half2*)&vD.z)));
            acc3 = __hadd2(acc3, __hadd2(__hadd2(*(__half2*)&vA.w, *(__half2*)&vB.w),
                                         __hadd2(*(__half2*)&vC.w, *(__half2*)&vD.w)));
        }
    }
    for (; e < s1; ++e) {
        int o = __ldg(&g_srcs[e]);
        if (act) {
            uint4 v = __ldg(XYin + o + lane);
            acc0 = __hadd2(acc0, *(__half2*)&v.x);
            acc1 = __hadd2(acc1, *(__half2*)&v.y);
            acc2 = __hadd2(acc2, *(__half2*)&v.z);
            acc3 = __hadd2(acc3, *(__half2*)&v.w);
        }
    }
    if (!act) return;

    float dinv = __ldg(&g_deginv[w]);
    float2 a0 = __half22float2(acc0);
    float2 a1 = __half22float2(acc1);
    float2 a2 = __half22float2(acc2);
    float2 a3 = __half22float2(acc3);
    float aggX[4] = {a0.x * dinv, a1.x * dinv, a2.x * dinv, a3.x * dinv};
    float aggY[4] = {a0.y * dinv, a1.y * dinv, a2.y * dinv, a3.y * dinv};

    int c0 = lane * 4;
    size_t rbase = (size_t)w * 24 + lane;
    uint4 sv = __ldg(XYin + rbase);
    float2 s0f = __half22float2(*(__half2*)&sv.x);
    float2 s1f = __half22float2(*(__half2*)&sv.y);
    float2 s2f = __half22float2(*(__half2*)&sv.z);
    float2 s3f = __half22float2(*(__half2*)&sv.w);

    float4 alv = *(const float4*)(al + c0);
    float4 bev = *(const float4*)(be + c0);
    float4 gav = *(const float4*)(ga + c0);
    float4 dev = *(const float4*)(de + c0);

    float Xn0 = s0f.x + DTC * s0f.x * (alv.x - bev.x * aggY[0]);
    float Yn0 = s0f.y + DTC * s0f.y * (-gav.x + dev.x * aggX[0]);
    float Xn1 = s1f.x + DTC * s1f.x * (alv.y - bev.y * aggY[1]);
    float Yn1 = s1f.y + DTC * s1f.y * (-gav.y + dev.y * aggX[1]);
    float Xn2 = s2f.x + DTC * s2f.x * (alv.z - bev.z * aggY[2]);
    float Yn2 = s2f.y + DTC * s2f.y * (-gav.z + dev.z * aggX[2]);
    float Xn3 = s3f.x + DTC * s3f.x * (alv.w - bev.w * aggY[3]);
    float Yn3 = s3f.y + DTC * s3f.y * (-gav.w + dev.w * aggX[3]);

    __half2 h0 = __floats2half2_rn(Xn0, Yn0);
    __half2 h1 = __floats2half2_rn(Xn1, Yn1);
    __half2 h2 = __floats2half2_rn(Xn2, Yn2);
    __half2 h3 = __floats2half2_rn(Xn3, Yn3);
    uint4 hv;
    hv.x = *(unsigned int*)&h0; hv.y = *(unsigned int*)&h1;
    hv.z = *(unsigned int*)&h2; hv.w = *(unsigned int*)&h3;
    XYout[rbase] = hv;
}

// ---------------- readout: out = [X|Y] @ Wr + br, fp16 state, f32x2 math ----
__global__ __launch_bounds__(128) void k_readout(
        const uint4* __restrict__ XY,
        const float* __restrict__ Wr, const float* __restrict__ br,
        float* __restrict__ out, int N) {
    __shared__ float2 xs2[128][33];
    __shared__ float  wsX[32][COUT];
    __shared__ float  wsY[32][COUT];
    int tid = threadIdx.x;
    int tx = tid & 7;
    int ty = tid >> 3;
    int row0 = blockIdx.x * 128;
    unsigned long long acc2[4][5];
#pragma unroll
    for (int p = 0; p < 4; ++p)
#pragma unroll
        for (int j = 0; j < 5; ++j) acc2[p][j] = 0ull;

    for (int kt = 0; kt < H; kt += 32) {
#pragma unroll
        for (int j = 0; j < 8; ++j) {
            int u4 = tid + j * 128;
            int r = u4 >> 3;
            int q = u4 & 7;
            int gr = row0 + r;
            uint4 v = make_uint4(0u, 0u, 0u, 0u);
            if (gr < N) v = __ldg(XY + (size_t)gr * 24 + (kt >> 2) + q);
            int cc = q * 4;
            xs2[r][cc + 0] = __half22float2(*(__half2*)&v.x);
            xs2[r][cc + 1] = __half22float2(*(__half2*)&v.y);
            xs2[r][cc + 2] = __half22float2(*(__half2*)&v.z);
            xs2[r][cc + 3] = __half22float2(*(__half2*)&v.w);
        }
#pragma unroll
        for (int j = 0; j < 10; ++j) {
            int idx = tid + j * 128;
            if (idx < 32 * COUT) {
                int k = idx / COUT;
                int c = idx - k * COUT;
                wsX[k][c] = Wr[(size_t)(kt + k) * COUT + c];
                wsY[k][c] = Wr[(size_t)(H + kt + k) * COUT + c];
            }
        }
        __syncthreads();
#pragma unroll
        for (int k = 0; k < 32; ++k) {
            float2 xv[8];
#pragma unroll
            for (int i = 0; i < 8; ++i) xv[i] = xs2[ty * 8 + i][k];
            unsigned long long XA[4], YA[4];
#pragma unroll
            for (int p = 0; p < 4; ++p) {
                XA[p] = packxy(xv[2 * p].x, xv[2 * p + 1].x);
                YA[p] = packxy(xv[2 * p].y, xv[2 * p + 1].y);
            }
#pragma unroll
            for (int j = 0; j < 5; ++j) {
                unsigned long long wxj = pack2(wsX[k][tx * 5 + j]);
                unsigned long long wyj = pack2(wsY[k][tx * 5 + j]);
#pragma unroll
                for (int p = 0; p < 4; ++p) {
                    ffma2(acc2[p][j], XA[p], wxj);
                    ffma2(acc2[p][j], YA[p], wyj);
                }
            }
        }
        __syncthreads();
    }
#pragma unroll
    for (int p = 0; p < 4; ++p) {
        int gr0 = row0 + ty * 8 + 2 * p;
#pragma unroll
        for (int j = 0; j < 5; ++j) {
            float vlo, vhi;
            unpack2(acc2[p][j], vlo, vhi);
            float bb = br[tx * 5 + j];
            if (gr0 < N)     out[(size_t)gr0 * COUT + tx * 5 + j] = vlo + bb;
            if (gr0 + 1 < N) out[(size_t)(gr0 + 1) * COUT + tx * 5 + j] = vhi + bb;
        }
    }
}

// ---------------- launch ----------------
extern "C" void kernel_launch(void* const* d_in, const int* in_sizes, int n_in,
                              void* d_out, int out_size) {
    const float* x  = (const float*)d_in[0];
    const int*   ei = (const int*)d_in[1];
    const float* Wx = (const float*)d_in[2];
    const float* bx = (const float*)d_in[3];
    const float* Wy = (const float*)d_in[4];
    const float* by = (const float*)d_in[5];
    const float* al = (const float*)d_in[6];
    const float* be = (const float*)d_in[7];
    const float* ga = (const float*)d_in[8];
    const float* de = (const float*)d_in[9];
    const float* Wr = (const float*)d_in[10];
    const float* br = (const float*)d_in[11];
    float* out = (float*)d_out;

    int N = in_sizes[0] / CIN;
    int E = in_sizes[1] / 2;
    if (N > NMAX) N = NMAX;
    if (E > EMAX) E = EMAX;
    const int* srcp = ei;
    const int* dstp = ei + E;

    // one-time side stream + fork/join events (no device memory involved)
    static cudaStream_t s2 = nullptr;
    static cudaEvent_t evF = nullptr, evJ = nullptr;
    if (s2 == nullptr) {
        cudaStreamCreateWithFlags(&s2, cudaStreamNonBlocking);
        cudaEventCreateWithFlags(&evF, cudaEventDisableTiming);
        cudaEventCreateWithFlags(&evJ, cudaEventDisableTiming);
    }

    void* degp;
    cudaGetSymbolAddress(&degp, g_deg);

    int NB = (N + 1023) >> 10;

    // fork: CSR chain on s2, lift on main stream (independent until layers)
    cudaEventRecord(evF, 0);
    cudaStreamWaitEvent(s2, evF, 0);

    cudaMemsetAsync(degp, 0, (size_t)N * sizeof(int), s2);
    k_deg<<<(E + 255) / 256, 256, 0, s2>>>(dstp, E);
    k_scan1<<<NB, 1024, 0, s2>>>(N);
    k_scan2<<<1, 64, 0, s2>>>(NB, N);
    k_scan3<<<(N + 255) / 256, 256, 0, s2>>>(N);
    k_scatter<<<(E + 255) / 256, 256, 0, s2>>>(srcp, dstp, E);
    cudaEventRecord(evJ, s2);

    dim3 gl((N + 127) / 128, 3);
    k_lift<<<gl, 256>>>(x, Wx, bx, Wy, by, N);

    // join: layers need both CSR and lifted state
    cudaStreamWaitEvent(0, evJ, 0);

    uint4* XYb[2];
    cudaGetSymbolAddress((void**)&XYb[0], g_XY0);
    cudaGetSymbolAddress((void**)&XYb[1], g_XY1);

    int layerBlocks = (N * 32 + 255) / 256;
    for (int l = 0; l < NLAYER; ++l) {
        k_layer<<<layerBlocks, 256>>>(XYb[l & 1], XYb[(l + 1) & 1],
                                      al + l * H, be + l * H, ga + l * H, de + l * H, N);
    }
    k_readout<<<(N + 127) / 128, 128>>>(XYb[NLAYER & 1], Wr, br, out, N);
}